// round 2
// baseline (speedup 1.0000x reference)
#include <cuda_runtime.h>

// bi_LSTM_47218870453093
//
// Output = softmax over a length-1 axis == exactly 1.0f for every element,
// independent of all inputs (see R1). Remaining cost is pure launch/replay
// overhead, so this round minimizes the kernel itself: one block, no
// parameters except the pointer, no predicates, compile-time-constant trip
// count, float4 stores.

// Fast path: exactly 4096 floats (B=4096, out [B,1]).
// 128 threads x 8 float4 = 4096 floats... no: 128 * 8 * 4 = 4096. Use 128x8.
__global__ __launch_bounds__(128, 1) void fill_ones_4096(float4* __restrict__ out) {
    const float4 v = make_float4(1.0f, 1.0f, 1.0f, 1.0f);
    int t = threadIdx.x;
    // 1024 float4 stores total; 128 threads, 8 each, fully unrolled,
    // coalesced stride-128 pattern.
#pragma unroll
    for (int k = 0; k < 8; ++k) {
        out[k * 128 + t] = v;
    }
}

// Generic fallback (defensive; out_size is 4096 for this problem).
__global__ void fill_ones_generic(float* __restrict__ out, int n) {
    int i = blockIdx.x * blockDim.x + threadIdx.x;
    if (i < n) out[i] = 1.0f;
}

extern "C" void kernel_launch(void* const* d_in, const int* in_sizes, int n_in,
                              void* d_out, int out_size) {
    (void)d_in; (void)in_sizes; (void)n_in;
    if (out_size == 4096) {
        fill_ones_4096<<<1, 128>>>(reinterpret_cast<float4*>(d_out));
    } else {
        int threads = 256;
        int blocks = (out_size + threads - 1) / threads;
        if (blocks < 1) blocks = 1;
        fill_ones_generic<<<blocks, threads>>>(reinterpret_cast<float*>(d_out), out_size);
    }
}